// round 1
// baseline (speedup 1.0000x reference)
#include <cuda_runtime.h>
#include <math.h>

// Problem constants (fixed shapes per metadata)
#define TT 2048          // tokens (B*S)
#define HH 1024          // hidden
#define EE 8             // experts
#define FF 3584          // ffn intermediate
#define TOPK 2
#define NPAIR (TT * TOPK)

// ---------------- scratch (static device globals; no allocation) ----------------
__device__ int   g_topk_idx[TT][TOPK];
__device__ float g_topk_w[TT][TOPK];
__device__ int   g_counts[EE];
__device__ int   g_offsets[EE];
__device__ int   g_pair_token[NPAIR];
__device__ float g_pair_w[NPAIR];
__device__ float g_act[(size_t)NPAIR * FF];   // ~58.7 MB intermediate activations

// ---------------- zero output ----------------
__global__ void zero_kernel(float* __restrict__ out, int n) {
    int i = blockIdx.x * blockDim.x + threadIdx.x;
    if (i < n) out[i] = 0.0f;
}

// ---------------- router: logits -> top2 -> renormalized weights ----------------
// One warp per token. Softmax+top2+renorm collapses to a 2-way logistic on the
// top-2 logits: w0 = 1/(1+exp(l1-l0)), w1 = 1-w0.
__global__ void router_kernel(const float* __restrict__ x, const float* __restrict__ gw) {
    int warp = (blockIdx.x * blockDim.x + threadIdx.x) >> 5;
    int lane = threadIdx.x & 31;
    if (warp >= TT) return;
    const float* xr = x + (size_t)warp * HH;

    float logit[EE];
#pragma unroll
    for (int e = 0; e < EE; e++) {
        const float* g = gw + (size_t)e * HH;
        float s = 0.0f;
        for (int i = lane; i < HH; i += 32) s += xr[i] * g[i];
#pragma unroll
        for (int o = 16; o > 0; o >>= 1) s += __shfl_xor_sync(0xffffffffu, s, o);
        logit[e] = s;
    }
    if (lane == 0) {
        int i0 = 0;
#pragma unroll
        for (int e = 1; e < EE; e++) if (logit[e] > logit[i0]) i0 = e;
        int i1 = (i0 == 0) ? 1 : 0;
#pragma unroll
        for (int e = 0; e < EE; e++) {
            if (e == i0) continue;
            if (logit[e] > logit[i1]) i1 = e;
        }
        float d = logit[i1] - logit[i0];   // <= 0
        float z = expf(d);
        float w0 = 1.0f / (1.0f + z);
        g_topk_idx[warp][0] = i0;
        g_topk_idx[warp][1] = i1;
        g_topk_w[warp][0] = w0;
        g_topk_w[warp][1] = z * w0;
    }
}

// ---------------- build per-expert compacted pair lists ----------------
__global__ void build_kernel() {
    __shared__ int s_cnt[EE];
    __shared__ int s_cur[EE];
    int tid = threadIdx.x;
    if (tid < EE) s_cnt[tid] = 0;
    __syncthreads();
    for (int p = tid; p < NPAIR; p += blockDim.x)
        atomicAdd(&s_cnt[g_topk_idx[p >> 1][p & 1]], 1);
    __syncthreads();
    if (tid == 0) {
        int off = 0;
        for (int e = 0; e < EE; e++) {
            g_offsets[e] = off;
            g_counts[e]  = s_cnt[e];
            s_cur[e]     = off;
            off += s_cnt[e];
        }
    }
    __syncthreads();
    for (int p = tid; p < NPAIR; p += blockDim.x) {
        int t = p >> 1, k = p & 1;
        int e = g_topk_idx[t][k];
        int slot = atomicAdd(&s_cur[e], 1);
        g_pair_token[slot] = t;
        g_pair_w[slot]     = g_topk_w[t][k];
    }
}

// ---------------- tiled fp32 grouped GEMMs ----------------
#define BM  128
#define BN  64
#define BKC 16

// act[p,f] = silu(x_g @ w1_e^T) * (x_g @ w3_e^T)
__global__ __launch_bounds__(256, 2)
void gemm1_kernel(const float* __restrict__ x,
                  const float* __restrict__ w1,
                  const float* __restrict__ w3) {
    int e    = blockIdx.z;
    int n_e  = g_counts[e];
    int row0 = blockIdx.y * BM;
    if (row0 >= n_e) return;
    int f0   = blockIdx.x * BN;
    int base = g_offsets[e];

    __shared__ float As [BKC][BM];
    __shared__ float Bs1[BKC][BN];
    __shared__ float Bs3[BKC][BN];
    __shared__ int   s_tok[BM];

    int tid = threadIdx.x;
    if (tid < BM) {
        int r = row0 + tid;
        s_tok[tid] = (r < n_e) ? g_pair_token[base + r] : 0;
    }
    __syncthreads();

    int tx = tid & 15;   // 16 groups along N (4 cols each)
    int ty = tid >> 4;   // 16 groups along M (8 rows each)

    float acc1[8][4], acc3[8][4];
#pragma unroll
    for (int i = 0; i < 8; i++)
#pragma unroll
        for (int j = 0; j < 4; j++) { acc1[i][j] = 0.0f; acc3[i][j] = 0.0f; }

    const float* w1b = w1 + ((size_t)e * FF + f0) * HH;
    const float* w3b = w3 + ((size_t)e * FF + f0) * HH;

    int ar0 = (tid      ) >> 2, ac0 = (tid      ) & 3;
    int ar1 = (tid + 256) >> 2, ac1 = (tid + 256) & 3;
    int bf  = tid >> 2,  bc4 = tid & 3;

    for (int k0 = 0; k0 < HH; k0 += BKC) {
        {
            float4 v = *(const float4*)(x + (size_t)s_tok[ar0] * HH + (k0 + ac0 * 4));
            As[ac0*4+0][ar0] = v.x; As[ac0*4+1][ar0] = v.y;
            As[ac0*4+2][ar0] = v.z; As[ac0*4+3][ar0] = v.w;
        }
        {
            float4 v = *(const float4*)(x + (size_t)s_tok[ar1] * HH + (k0 + ac1 * 4));
            As[ac1*4+0][ar1] = v.x; As[ac1*4+1][ar1] = v.y;
            As[ac1*4+2][ar1] = v.z; As[ac1*4+3][ar1] = v.w;
        }
        {
            float4 v1 = *(const float4*)(w1b + (size_t)bf * HH + (k0 + bc4 * 4));
            float4 v3 = *(const float4*)(w3b + (size_t)bf * HH + (k0 + bc4 * 4));
            Bs1[bc4*4+0][bf] = v1.x; Bs1[bc4*4+1][bf] = v1.y;
            Bs1[bc4*4+2][bf] = v1.z; Bs1[bc4*4+3][bf] = v1.w;
            Bs3[bc4*4+0][bf] = v3.x; Bs3[bc4*4+1][bf] = v3.y;
            Bs3[bc4*4+2][bf] = v3.z; Bs3[bc4*4+3][bf] = v3.w;
        }
        __syncthreads();
#pragma unroll
        for (int kk = 0; kk < BKC; kk++) {
            float a[8], b1[4], b3[4];
            *(float4*)&a[0]  = *(const float4*)&As[kk][ty * 8];
            *(float4*)&a[4]  = *(const float4*)&As[kk][ty * 8 + 4];
            *(float4*)&b1[0] = *(const float4*)&Bs1[kk][tx * 4];
            *(float4*)&b3[0] = *(const float4*)&Bs3[kk][tx * 4];
#pragma unroll
            for (int i = 0; i < 8; i++)
#pragma unroll
                for (int j = 0; j < 4; j++) {
                    acc1[i][j] += a[i] * b1[j];
                    acc3[i][j] += a[i] * b3[j];
                }
        }
        __syncthreads();
    }

#pragma unroll
    for (int i = 0; i < 8; i++) {
        int r = row0 + ty * 8 + i;
        if (r >= n_e) continue;
        float4 o;
        float g, u;
        g = acc1[i][0]; u = acc3[i][0]; o.x = (g / (1.0f + expf(-g))) * u;
        g = acc1[i][1]; u = acc3[i][1]; o.y = (g / (1.0f + expf(-g))) * u;
        g = acc1[i][2]; u = acc3[i][2]; o.z = (g / (1.0f + expf(-g))) * u;
        g = acc1[i][3]; u = acc3[i][3]; o.w = (g / (1.0f + expf(-g))) * u;
        *(float4*)(g_act + (size_t)(base + r) * FF + (f0 + tx * 4)) = o;
    }
}

// out[tok,:] += w_pair * (act[p,:] @ w2_e^T)
// Exactly two commutative fp32 atomicAdds land on each out element -> deterministic.
__global__ __launch_bounds__(256, 2)
void gemm2_kernel(const float* __restrict__ w2, float* __restrict__ out) {
    int e    = blockIdx.z;
    int n_e  = g_counts[e];
    int row0 = blockIdx.y * BM;
    if (row0 >= n_e) return;
    int h0   = blockIdx.x * BN;
    int base = g_offsets[e];

    __shared__ float As[BKC][BM];
    __shared__ float Bs[BKC][BN];

    int tid = threadIdx.x;
    int tx = tid & 15;
    int ty = tid >> 4;

    float acc[8][4];
#pragma unroll
    for (int i = 0; i < 8; i++)
#pragma unroll
        for (int j = 0; j < 4; j++) acc[i][j] = 0.0f;

    const float* w2b = w2 + ((size_t)e * HH + h0) * FF;

    int ar0 = (tid      ) >> 2, ac0 = (tid      ) & 3;
    int ar1 = (tid + 256) >> 2, ac1 = (tid + 256) & 3;
    int bh  = tid >> 2,  bc4 = tid & 3;

    int grow0 = base + row0 + ar0; if (grow0 > NPAIR - 1) grow0 = NPAIR - 1;
    int grow1 = base + row0 + ar1; if (grow1 > NPAIR - 1) grow1 = NPAIR - 1;

    for (int k0 = 0; k0 < FF; k0 += BKC) {
        {
            float4 v = *(const float4*)(g_act + (size_t)grow0 * FF + (k0 + ac0 * 4));
            As[ac0*4+0][ar0] = v.x; As[ac0*4+1][ar0] = v.y;
            As[ac0*4+2][ar0] = v.z; As[ac0*4+3][ar0] = v.w;
        }
        {
            float4 v = *(const float4*)(g_act + (size_t)grow1 * FF + (k0 + ac1 * 4));
            As[ac1*4+0][ar1] = v.x; As[ac1*4+1][ar1] = v.y;
            As[ac1*4+2][ar1] = v.z; As[ac1*4+3][ar1] = v.w;
        }
        {
            float4 v = *(const float4*)(w2b + (size_t)bh * FF + (k0 + bc4 * 4));
            Bs[bc4*4+0][bh] = v.x; Bs[bc4*4+1][bh] = v.y;
            Bs[bc4*4+2][bh] = v.z; Bs[bc4*4+3][bh] = v.w;
        }
        __syncthreads();
#pragma unroll
        for (int kk = 0; kk < BKC; kk++) {
            float a[8], b[4];
            *(float4*)&a[0] = *(const float4*)&As[kk][ty * 8];
            *(float4*)&a[4] = *(const float4*)&As[kk][ty * 8 + 4];
            *(float4*)&b[0] = *(const float4*)&Bs[kk][tx * 4];
#pragma unroll
            for (int i = 0; i < 8; i++)
#pragma unroll
                for (int j = 0; j < 4; j++) acc[i][j] += a[i] * b[j];
        }
        __syncthreads();
    }

#pragma unroll
    for (int i = 0; i < 8; i++) {
        int r = row0 + ty * 8 + i;
        if (r >= n_e) continue;
        int prow = base + r;
        int tok  = g_pair_token[prow];
        float wt = g_pair_w[prow];
        float* op = out + (size_t)tok * HH + (h0 + tx * 4);
        atomicAdd(op + 0, acc[i][0] * wt);
        atomicAdd(op + 1, acc[i][1] * wt);
        atomicAdd(op + 2, acc[i][2] * wt);
        atomicAdd(op + 3, acc[i][3] * wt);
    }
}

// ---------------- launch ----------------
extern "C" void kernel_launch(void* const* d_in, const int* in_sizes, int n_in,
                              void* d_out, int out_size) {
    (void)in_sizes; (void)n_in; (void)out_size;
    const float* x  = (const float*)d_in[0];   // hidden_states [1,2048,1024]
    const float* gw = (const float*)d_in[1];   // gate_w [8,1024]
    const float* w1 = (const float*)d_in[2];   // [8,3584,1024]
    const float* w3 = (const float*)d_in[3];   // [8,3584,1024]
    const float* w2 = (const float*)d_in[4];   // [8,1024,3584]
    float* out = (float*)d_out;                // [1,2048,1024]

    zero_kernel<<<(TT * HH + 255) / 256, 256>>>(out, TT * HH);
    router_kernel<<<TT / 8, 256>>>(x, gw);     // 8 warps/block, 1 warp/token
    build_kernel<<<1, 256>>>();

    dim3 g1(FF / BN, TT / BM, EE);             // (56, 16, 8); dead tiles early-exit
    gemm1_kernel<<<g1, 256>>>(x, w1, w3);

    dim3 g2(HH / BN, TT / BM, EE);             // (16, 16, 8)
    gemm2_kernel<<<g2, 256>>>(w2, out);
}